// round 9
// baseline (speedup 1.0000x reference)
#include <cuda_runtime.h>
#include <math.h>

#define NN    512
#define BIT   64
#define NCLS  100
#define ALPHA 5.0f
#define LAM   1.0f
#define NB    NN                // 512 blocks, one anchor row each
#define NT    256               // threads per block

// Scratch (allocation-free: __device__ globals)
__device__ float4 g_part[NB];    // {rowloss_or_0, valid, l2partial, 0} per block
__device__ unsigned int g_done = 0;

// ---------------------------------------------------------------------------
// Single fused kernel, one anchor row per block (512 blocks -> 4096 warps,
// grid-limited occupancy doubles vs R8). Last block reduces + writes output.
// ---------------------------------------------------------------------------
__global__ void __launch_bounds__(NT) fused_kernel(const float* __restrict__ u,
                                                   const float* __restrict__ y,
                                                   float* __restrict__ out) {
    __shared__ float4 s_ur[BIT / 4];               // anchor row of u      (256 B)
    __shared__ float  s_ip[NN];                    // ip row               (2 KB)
    __shared__ unsigned char s_isneg[NN];          // negative mask        (512 B)
    __shared__ int    s_lbl;
    __shared__ unsigned s_gmask[16];               // pos bitmask words
    __shared__ short  s_poslist[NN];               // positive indices     (1 KB)
    __shared__ int    s_npos;
    __shared__ float  s_part[8];                   // per-warp pair partials
    __shared__ float  s_s2[2];                     // loss2 partials (2 warps)
    __shared__ int    s_islast;
    __shared__ float4 s_rf[NT];                    // final reduce scratch (4 KB)

    const int tid  = threadIdx.x;
    const int bid  = blockIdx.x;
    const int r    = bid;                          // anchor row
    const int lane = tid & 31;
    const int wrp  = tid >> 5;

    // --- phase 0: anchor row of u into smem + label recovery (one-hot) ---
    if (tid < BIT / 4) {                           // 16 float4 loads
        s_ur[tid] = ((const float4*)(u + (size_t)r * BIT))[tid];
    }
    if (tid < NCLS) {                              // exactly one writer
        if (y[(size_t)r * NCLS + tid] > 0.5f) s_lbl = tid;
    }
    __syncthreads();

    const int j1 = tid;
    const int j2 = tid + NT;
    const int lbl = s_lbl;

    // --- scattered isneg gathers issued EARLY; hide under the dot loop ---
    const float yv1 = __ldg(y + (size_t)j1 * NCLS + lbl);
    const float yv2 = __ldg(y + (size_t)j2 * NCLS + lbl);

    // --- dot products: ip[r][j1], ip[r][j2] ---
    {
        const float4* __restrict__ uj1 = (const float4*)(u + (size_t)j1 * BIT);
        const float4* __restrict__ uj2 = (const float4*)(u + (size_t)j2 * BIT);
        float a1 = 0.f, a2 = 0.f;
        #pragma unroll 4
        for (int k = 0; k < BIT / 4; ++k) {
            float4 b1 = uj1[k];
            float4 b2 = uj2[k];
            float4 c  = s_ur[k];
            a1 += c.x * b1.x + c.y * b1.y + c.z * b1.z + c.w * b1.w;
            a2 += c.x * b2.x + c.y * b2.y + c.z * b2.z + c.w * b2.w;
        }
        s_ip[j1] = a1;
        s_ip[j2] = a2;
    }

    // --- isneg from prefetched values (one-hot: exact 0/1) ---
    const unsigned char n1 = (yv1 == 0.0f) ? 1 : 0;
    const unsigned char n2 = (yv2 == 0.0f) ? 1 : 0;
    s_isneg[j1] = n1;
    s_isneg[j2] = n2;

    // --- positive bitmasks straight from registers ---
    {
        unsigned m;
        m = __ballot_sync(0xffffffffu, n1 == 0);   // j = wrp*32+lane
        if (lane == 0) s_gmask[wrp] = m;
        m = __ballot_sync(0xffffffffu, n2 == 0);   // j = 256 + wrp*32+lane
        if (lane == 0) s_gmask[wrp + 8] = m;
    }

    // --- loss2 partial: this block's BIT = 64 u values (from smem copy) ---
    if (tid < BIT) {
        float v  = ((const float*)s_ur)[tid];
        float sg = (v > 0.0f) ? 1.0f : ((v < 0.0f) ? -1.0f : 0.0f);
        float d  = v - sg;
        float s2 = d * d;
        #pragma unroll
        for (int o = 16; o > 0; o >>= 1) s2 += __shfl_xor_sync(0xffffffffu, s2, o);
        if (lane == 0) s_s2[wrp] = s2;
    }
    __syncthreads();

    // --- deterministic compaction by thread 0 (~npos ~ 5 pops) ---
    if (tid == 0) {
        int cnt = 0;
        #pragma unroll
        for (int c = 0; c < 16; ++c) {
            unsigned m = s_gmask[c];
            while (m) {
                int b = __ffs(m) - 1;
                s_poslist[cnt++] = (short)(c * 32 + b);
                m &= m - 1;
            }
        }
        s_npos = cnt;
    }
    __syncthreads();

    // --- pair loop: (p in pos(r)) x (n in 0..511), n filtered by isneg ---
    const int npos  = s_npos;
    const int total = npos << 9;
    float acc = 0.0f;
    for (int idx = tid; idx < total; idx += NT) {
        int p = s_poslist[idx >> 9];
        int n = idx & (NN - 1);
        if (s_isneg[n]) {
            float t = s_ip[p] - s_ip[n] - ALPHA;
            t = fminf(fmaxf(t, -100.0f), 50.0f);
            // log1p(exp(t)) - t == log(1 + exp(-|t|)) + max(-t, 0)
            acc += __logf(1.0f + __expf(-fabsf(t))) + fmaxf(-t, 0.0f);
        }
    }
    #pragma unroll
    for (int o = 16; o > 0; o >>= 1) acc += __shfl_xor_sync(0xffffffffu, acc, o);
    if (lane == 0) s_part[wrp] = acc;
    __syncthreads();

    // --- block epilogue: row loss + loss2 partial, publish, count arrival ---
    if (tid == 0) {
        int   np = npos;
        int   nn = NN - np;
        float rs = 0.0f;
        #pragma unroll
        for (int w2 = 0; w2 < 8; ++w2) rs += s_part[w2];
        float rl    = rs / fmaxf((float)(np * nn), 1.0f);
        float valid = (np > 0 && nn > 0) ? 1.0f : 0.0f;
        float bl2   = s_s2[0] + s_s2[1];

        g_part[bid] = make_float4(valid * rl, valid, bl2, 0.0f);
        __threadfence();
        unsigned prev = atomicAdd(&g_done, 1u);
        s_islast = (prev == NB - 1) ? 1 : 0;
    }
    __syncthreads();

    // --- last block performs the final deterministic reduction ---
    if (s_islast) {
        float4 a = __ldcg(&g_part[tid]);
        float4 b = __ldcg(&g_part[tid + NT]);
        s_rf[tid] = make_float4(a.x + b.x, a.y + b.y, a.z + b.z, 0.0f);
        __syncthreads();
        #pragma unroll
        for (int s = NT / 2; s > 0; s >>= 1) {
            if (tid < s) {
                float4 x0 = s_rf[tid];
                float4 x1 = s_rf[tid + s];
                s_rf[tid] = make_float4(x0.x + x1.x, x0.y + x1.y, x0.z + x1.z, 0.0f);
            }
            __syncthreads();
        }
        if (tid == 0) {
            float4 rres = s_rf[0];
            float count = rres.y;
            float loss1 = (count > 0.0f) ? (rres.x / fmaxf(count, 1.0f)) : 0.0f;
            float loss2 = LAM * rres.z / (float)(NN * BIT);
            out[0] = loss1 + loss2;
            g_done = 0;   // reset for next graph replay (safe: we are last)
        }
    }
}

// ---------------------------------------------------------------------------
extern "C" void kernel_launch(void* const* d_in, const int* in_sizes, int n_in,
                              void* d_out, int out_size) {
    const float* u;
    const float* y;
    if (in_sizes[0] == NN * BIT) {
        u = (const float*)d_in[0];
        y = (const float*)d_in[1];
    } else {
        u = (const float*)d_in[1];
        y = (const float*)d_in[0];
    }
    float* out = (float*)d_out;

    fused_kernel<<<NB, NT>>>(u, y, out);
}

// round 10
// speedup vs baseline: 1.7405x; 1.7405x over previous
#include <cuda_runtime.h>
#include <math.h>

#define NN    512
#define BIT   64
#define NCLS  100
#define ALPHA 5.0f
#define LAM   1.0f
#define NB    NN                // 512 blocks, one anchor row each
#define NT    256               // threads per block

// Scratch (allocation-free: __device__ globals)
__device__ float4 g_part[NB];    // {rowloss_or_0, valid, l2partial, 0} per block
__device__ unsigned int g_done = 0;

// ---------------------------------------------------------------------------
// Single fused kernel, one anchor row per block. R10: the ip phase loads u
// COALESCED (flat float4 sweep, 4 lines/warp-instr instead of 32) and reduces
// 16-lane segments with shfl_xor. Last block reduces partials + writes out.
// ---------------------------------------------------------------------------
__global__ void __launch_bounds__(NT) fused_kernel(const float* __restrict__ u,
                                                   const float* __restrict__ y,
                                                   float* __restrict__ out) {
    __shared__ float4 s_ur[BIT / 4];               // anchor row of u      (256 B)
    __shared__ float  s_ip[NN];                    // ip row               (2 KB)
    __shared__ unsigned char s_isneg[NN];          // negative mask        (512 B)
    __shared__ int    s_lbl;
    __shared__ unsigned s_gmask[16];               // pos bitmask words
    __shared__ short  s_poslist[NN];               // positive indices     (1 KB)
    __shared__ int    s_npos;
    __shared__ float  s_part[8];                   // per-warp pair partials
    __shared__ float  s_s2[2];                     // loss2 partials (2 warps)
    __shared__ int    s_islast;
    __shared__ float4 s_rf[NT];                    // final reduce scratch (4 KB)

    const int tid  = threadIdx.x;
    const int bid  = blockIdx.x;
    const int r    = bid;                          // anchor row
    const int lane = tid & 31;
    const int wrp  = tid >> 5;

    // --- phase 0: anchor row of u into smem + label recovery (one-hot) ---
    if (tid < BIT / 4) {                           // 16 float4 loads
        s_ur[tid] = ((const float4*)(u + (size_t)r * BIT))[tid];
    }
    if (tid < NCLS) {                              // exactly one writer
        if (y[(size_t)r * NCLS + tid] > 0.5f) s_lbl = tid;
    }
    __syncthreads();

    const int lbl = s_lbl;

    // --- scattered isneg gathers issued EARLY; hide under the dot loop ---
    const float yv1 = __ldg(y + (size_t)tid * NCLS + lbl);
    const float yv2 = __ldg(y + (size_t)(tid + NT) * NCLS + lbl);

    // --- coalesced dot phase -------------------------------------------------
    // Thread t owns anchor cols (t%16)*4..+3 (constant across iterations).
    // Iteration it: block loads u rows [it*16, it*16+16) as a flat coalesced
    // float4 sweep; 16-lane segment reduction yields 16 ip values per iter.
    {
        const float4 av = s_ur[tid & 15];
        const int seg = tid & 15;                  // col segment within row
        const int row_in_iter = tid >> 4;          // 0..15
        #pragma unroll 4
        for (int it = 0; it < NN / 16; ++it) {
            float4 b = ((const float4*)u)[it * (16 * BIT / 4) + tid];
            float p = av.x * b.x + av.y * b.y + av.z * b.z + av.w * b.w;
            p += __shfl_xor_sync(0xffffffffu, p, 1);
            p += __shfl_xor_sync(0xffffffffu, p, 2);
            p += __shfl_xor_sync(0xffffffffu, p, 4);
            p += __shfl_xor_sync(0xffffffffu, p, 8);
            if (seg == 0) s_ip[it * 16 + row_in_iter] = p;
        }
    }

    // --- isneg from prefetched values (one-hot: exact 0/1) ---
    const unsigned char n1 = (yv1 == 0.0f) ? 1 : 0;
    const unsigned char n2 = (yv2 == 0.0f) ? 1 : 0;
    s_isneg[tid]      = n1;
    s_isneg[tid + NT] = n2;

    // --- positive bitmasks straight from registers ---
    {
        unsigned m;
        m = __ballot_sync(0xffffffffu, n1 == 0);   // j = wrp*32+lane
        if (lane == 0) s_gmask[wrp] = m;
        m = __ballot_sync(0xffffffffu, n2 == 0);   // j = 256 + wrp*32+lane
        if (lane == 0) s_gmask[wrp + 8] = m;
    }

    // --- loss2 partial: this block's BIT = 64 u values (from smem copy) ---
    if (tid < BIT) {
        float v  = ((const float*)s_ur)[tid];
        float sg = (v > 0.0f) ? 1.0f : ((v < 0.0f) ? -1.0f : 0.0f);
        float d  = v - sg;
        float s2 = d * d;
        #pragma unroll
        for (int o = 16; o > 0; o >>= 1) s2 += __shfl_xor_sync(0xffffffffu, s2, o);
        if (lane == 0) s_s2[wrp] = s2;
    }
    __syncthreads();

    // --- deterministic compaction by thread 0 (~npos ~ 5 pops) ---
    if (tid == 0) {
        int cnt = 0;
        #pragma unroll
        for (int c = 0; c < 16; ++c) {
            unsigned m = s_gmask[c];
            while (m) {
                int b = __ffs(m) - 1;
                s_poslist[cnt++] = (short)(c * 32 + b);
                m &= m - 1;
            }
        }
        s_npos = cnt;
    }
    __syncthreads();

    // --- pair loop: (p in pos(r)) x (n in 0..511), n filtered by isneg ---
    const int npos  = s_npos;
    const int total = npos << 9;
    float acc = 0.0f;
    for (int idx = tid; idx < total; idx += NT) {
        int p = s_poslist[idx >> 9];
        int n = idx & (NN - 1);
        if (s_isneg[n]) {
            float t = s_ip[p] - s_ip[n] - ALPHA;
            t = fminf(fmaxf(t, -100.0f), 50.0f);
            // log1p(exp(t)) - t == log(1 + exp(-|t|)) + max(-t, 0)
            acc += __logf(1.0f + __expf(-fabsf(t))) + fmaxf(-t, 0.0f);
        }
    }
    #pragma unroll
    for (int o = 16; o > 0; o >>= 1) acc += __shfl_xor_sync(0xffffffffu, acc, o);
    if (lane == 0) s_part[wrp] = acc;
    __syncthreads();

    // --- block epilogue: row loss + loss2 partial, publish, count arrival ---
    if (tid == 0) {
        int   np = npos;
        int   nn = NN - np;
        float rs = 0.0f;
        #pragma unroll
        for (int w2 = 0; w2 < 8; ++w2) rs += s_part[w2];
        float rl    = rs / fmaxf((float)(np * nn), 1.0f);
        float valid = (np > 0 && nn > 0) ? 1.0f : 0.0f;
        float bl2   = s_s2[0] + s_s2[1];

        g_part[bid] = make_float4(valid * rl, valid, bl2, 0.0f);
        __threadfence();
        unsigned prev = atomicAdd(&g_done, 1u);
        s_islast = (prev == NB - 1) ? 1 : 0;
    }
    __syncthreads();

    // --- last block performs the final deterministic reduction ---
    if (s_islast) {
        float4 a = __ldcg(&g_part[tid]);
        float4 b = __ldcg(&g_part[tid + NT]);
        s_rf[tid] = make_float4(a.x + b.x, a.y + b.y, a.z + b.z, 0.0f);
        __syncthreads();
        #pragma unroll
        for (int s = NT / 2; s > 0; s >>= 1) {
            if (tid < s) {
                float4 x0 = s_rf[tid];
                float4 x1 = s_rf[tid + s];
                s_rf[tid] = make_float4(x0.x + x1.x, x0.y + x1.y, x0.z + x1.z, 0.0f);
            }
            __syncthreads();
        }
        if (tid == 0) {
            float4 rres = s_rf[0];
            float count = rres.y;
            float loss1 = (count > 0.0f) ? (rres.x / fmaxf(count, 1.0f)) : 0.0f;
            float loss2 = LAM * rres.z / (float)(NN * BIT);
            out[0] = loss1 + loss2;
            g_done = 0;   // reset for next graph replay (safe: we are last)
        }
    }
}

// ---------------------------------------------------------------------------
extern "C" void kernel_launch(void* const* d_in, const int* in_sizes, int n_in,
                              void* d_out, int out_size) {
    const float* u;
    const float* y;
    if (in_sizes[0] == NN * BIT) {
        u = (const float*)d_in[0];
        y = (const float*)d_in[1];
    } else {
        u = (const float*)d_in[1];
        y = (const float*)d_in[0];
    }
    float* out = (float*)d_out;

    fused_kernel<<<NB, NT>>>(u, y, out);
}